// round 16
// baseline (speedup 1.0000x reference)
#include <cuda_runtime.h>
#include <math.h>

#define NFFT 512
#define HOP  128
#define LSIG 160000
#define BB   16
#define CC   4
#define TT   1251
#define FDIM 257
#define KFEAT (4 * CC * FDIM)   // 4112
#define CF   (CC * FDIM)        // 1028

#define PI_D 3.14159265358979323846
#define SVCOEF ((float)(-2.0 * PI_D * 16000.0 / (512.0 * 340.4)))

// pass1->pass2 skew stride: 72 = 8 (mod 16) -> conflict-free (proven R11)
#define SDS 72
// pass2->pass3 exchange (split 4B planes): injective, conflict-free both ways
#define EXI(k0, kk, nn) (72 * (k0) + 8 * (kk) + ((nn) ^ (kk)))
// natural-order diagonal skew (proven R11): injective, conflict-free
#define NSK(a) ((a) + 4 * ((a) >> 5))

struct c2 { float x, y; };

__device__ __forceinline__ c2 cmul(c2 a, c2 b){ c2 r; r.x = a.x*b.x - a.y*b.y; r.y = a.x*b.y + a.y*b.x; return r; }
__device__ __forceinline__ c2 cadd(c2 a, c2 b){ c2 r; r.x = a.x+b.x; r.y = a.y+b.y; return r; }
__device__ __forceinline__ c2 csub(c2 a, c2 b){ c2 r; r.x = a.x-b.x; r.y = a.y-b.y; return r; }
__device__ __forceinline__ c2 mulnegi(c2 a){ c2 r; r.x = a.y; r.y = -a.x; return r; }

// radix-8 DFT: o[k] = sum_j v[j] * w8^{j*k}, w8 = exp(-2*pi*i/8)
__device__ __forceinline__ void radix8(const c2* v, c2* o) {
    const float S = 0.70710678118654752f;
    c2 a0=cadd(v[0],v[4]), a1=csub(v[0],v[4]);
    c2 a2=cadd(v[2],v[6]), a3=csub(v[2],v[6]);
    c2 b0=cadd(v[1],v[5]), b1=csub(v[1],v[5]);
    c2 b2=cadd(v[3],v[7]), b3=csub(v[3],v[7]);
    c2 ia3 = mulnegi(a3), ib3 = mulnegi(b3);
    c2 c0=cadd(a0,a2), c1=csub(a0,a2);
    c2 e2=cadd(a1,ia3), e3=csub(a1,ia3);
    c2 d0=cadd(b0,b2), d1=csub(b0,b2);
    c2 d2=cadd(b1,ib3), d3=csub(b1,ib3);
    c2 w1d2; w1d2.x = S*(d2.x + d2.y); w1d2.y = S*(d2.y - d2.x);
    c2 w3d3; w3d3.x = S*(d3.y - d3.x); w3d3.y = -S*(d3.x + d3.y);
    c2 id1 = mulnegi(d1);
    o[0]=cadd(c0,d0);    o[4]=csub(c0,d0);
    o[2]=cadd(c1,id1);   o[6]=csub(c1,id1);
    o[1]=cadd(e2,w1d2);  o[5]=csub(e2,w1d2);
    o[3]=cadd(e3,w3d3);  o[7]=csub(e3,w3d3);
}

// ---------------------------------------------------------------------------
// Single fused kernel: TDOA (threads 0-63, piggybacks on existing barriers) +
// STFT (4 FFT units of 64 thr; 3 radix-8 register passes, conflict-free
// exchanges) + paired-k epilogue with STG.64 stores (no staging, no barrier).
// ---------------------------------------------------------------------------
__global__ void __launch_bounds__(256) stft_kernel(const float* __restrict__ x,
                                                   const float* __restrict__ angle,
                                                   const float* __restrict__ mic_pos,
                                                   float* __restrict__ out) {
    __shared__ c2 sd[4][576];        // p1->p2 skew 72; reused as nat planes
    __shared__ float exR[4][572];    // p2->p3 exchange, real plane
    __shared__ float exI[4][572];    // p2->p3 exchange, imag plane
    __shared__ float d2s[BB * CC];   // TDOA partials
    __shared__ float dts[CC];        // tdoa[c]

    const int tid = threadIdx.x;
    const int u   = tid >> 6;        // FFT unit 0..3
    const int tau = tid & 63;
    const int t   = blockIdx.x * 4 + u;
    const int by  = blockIdx.y;
    const int b   = by >> 1;
    const int pr  = by & 1;          // channel pair (2pr, 2pr+1)
    const bool active = (t < TT);

    // nat planes alias sd[u] (1152 floats): natR at 0 (max 571), natI at 576
    float* natR = reinterpret_cast<float*>(sd[u]);
    float* natI = natR + 576;

    c2 v[8], o8[8];

    // ---- TDOA partials (threads 0-63; accurate trig for the angle) ----
    if (tid < BB * CC) {
        const int bb = tid >> 2;
        // exact fp32 values of sinf/cosf(float(pi/2)) — reference quirk
        const float sin90 = 1.0f;
        const float cos90 = -4.37113883e-08f;
        float rad = -angle[bb] * (float)(PI_D / 180.0);
        float sr_, cr_;
        sincosf(rad, &sr_, &cr_);
        float lx = cr_ * sin90;
        float ly = sr_ * sin90;
        float lz = cos90;              // DIST = 1.0
        const float* mp = mic_pos + tid * 3;
        float dx = mp[0] - lx, dy = mp[1] - ly, dz = mp[2] - lz;
        d2s[tid] = dx * dx + dy * dy + dz * dz;
    }

    // ---- pass 1: windowed load, radix-8 over n2, twiddle W64^{n1*k0} ----
    if (active) {
        const float S = 0.70710678118654752f;
        const float c8[8] = {1.f,  S, 0.f, -S, -1.f, -S,  0.f,  S};
        const float s8[8] = {0.f,  S, 1.f,  S,  0.f, -S, -1.f, -S};
        float sth, cth;
        __sincosf((float)(2.0 * PI_D / 512.0) * (float)tau, &sth, &cth);

        const float* xa = x + (size_t)(b * CC + 2 * pr) * LSIG;
        const float* xb = xa + LSIG;
        const int p0 = t * HOP - 256;
        if (t >= 2 && t <= 1248) {           // interior: no reflection possible
#pragma unroll
            for (int n2 = 0; n2 < 8; n2++) {
                int si = p0 + n2 * 64 + tau;
                float cosn = c8[n2] * cth - s8[n2] * sth;    // cos(2*pi*n/512)
                float w = 0.5f - 0.5f * cosn;                // Hann
                v[n2].x = xa[si] * w;
                v[n2].y = xb[si] * w;
            }
        } else {
#pragma unroll
            for (int n2 = 0; n2 < 8; n2++) {
                int p = p0 + n2 * 64 + tau;
                int si = (p < 0) ? -p : ((p >= LSIG) ? 2 * LSIG - 2 - p : p);
                float cosn = c8[n2] * cth - s8[n2] * sth;
                float w = 0.5f - 0.5f * cosn;
                v[n2].x = xa[si] * w;
                v[n2].y = xb[si] * w;
            }
        }
        radix8(v, o8);
        int n1 = tau >> 3;
        float ss, cs;
        __sincosf((float)(-2.0 * PI_D / 64.0) * (float)n1, &ss, &cs);
        c2 step; step.x = cs; step.y = ss;                   // W64^{n1}
        c2 w; w.x = 1.f; w.y = 0.f;
#pragma unroll
        for (int k0 = 0; k0 < 8; k0++) {
            sd[u][k0 * SDS + tau] = cmul(o8[k0], w);         // * W64^{n1*k0}
            w = cmul(w, step);
        }
    }
    __syncthreads();

    // ---- TDOA reduce (rides the pass-1 barrier; read after barrier 3) ----
    if (tid < CC) {
        float ssum = 0.f;
        for (int bb = 0; bb < BB; bb++) ssum += d2s[bb * CC + tid];
        dts[tid] = sqrtf(ssum);
    }

    // ---- pass 2: radix-8 over n1, twiddle, write exchange planes ----
    if (active) {
        const int k0 = tau >> 3;
        const int n0 = tau & 7;
#pragma unroll
        for (int n1 = 0; n1 < 8; n1++) v[n1] = sd[u][k0 * SDS + n1 * 8 + n0];
        radix8(v, o8);
        float s0, c0, ss, cs;
        __sincosf((float)(-2.0 * PI_D / 512.0) * (float)(n0 * k0), &s0, &c0);
        __sincosf((float)(-2.0 * PI_D / 64.0) * (float)n0, &ss, &cs);
        c2 w;    w.x = c0;   w.y = s0;                       // W512^{n0*k0}
        c2 step; step.x = cs; step.y = ss;                   // W64^{n0}
#pragma unroll
        for (int k1 = 0; k1 < 8; k1++) {
            c2 r = cmul(o8[k1], w);
            int e = EXI(k0, k1, n0);
            exR[u][e] = r.x;
            exI[u][e] = r.y;
            w = cmul(w, step);
        }
    }
    __syncthreads();   // pass-2 reads of sd complete -> sd reusable as nat

    // ---- pass 3: read exchange, radix-8 over n0, NSK planes into sd ----
    if (active) {
        const int k0 = tau >> 3;
        const int l  = tau & 7;      // = k1
#pragma unroll
        for (int n0 = 0; n0 < 8; n0++) {
            int e = EXI(k0, l, n0);
            v[n0].x = exR[u][e];
            v[n0].y = exI[u][e];
        }
        radix8(v, o8);               // o8[k2] = X[64*k2 + 8*l + k0]
#pragma unroll
        for (int k2 = 0; k2 < 8; k2++) {
            int a  = k2 * 64 + l * 8 + k0;
            int sa = NSK(a);
            natR[sa] = o8[k2].x;
            natI[sa] = o8[k2].y;
        }
    }
    __syncthreads();

    // ---- paired-k epilogue: unpack + sv, STG.64 stores, no staging ----
    if (active) {
        float* row = out + ((size_t)b * TT + t) * KFEAT;
        const int ca = 2 * pr, cb = 2 * pr + 1;
        const float dta = dts[ca] - dts[0];
        const float dtb = dts[cb] - dts[0];
        float* aBase = row + ca * FDIM;     // even element offset
        float* bBase = row + cb * FDIM;     // odd element offset

        // sv rotation chains (all values carry the 0.5 normalization in sa/sb)
        c2 sa, sb, stepA, stepB, rotA, rotB;
        __sincosf(SVCOEF * (float)(2 * tau) * dta, &sa.y, &sa.x);
        __sincosf(SVCOEF * (float)(2 * tau + 1) * dtb, &sb.y, &sb.x);
        sa.x *= 0.5f; sa.y *= 0.5f;
        sb.x *= 0.5f; sb.y *= 0.5f;
        __sincosf(SVCOEF * dta, &stepA.y, &stepA.x);           // +1 bin
        __sincosf(SVCOEF * dtb, &stepB.y, &stepB.x);
        __sincosf(SVCOEF * 128.f * dta, &rotA.y, &rotA.x);     // +128 bins
        __sincosf(SVCOEF * 128.f * dtb, &rotB.y, &rotB.x);

#pragma unroll
        for (int it = 0; it < 2; it++) {
            const int k2a = 2 * (tau + 64 * it);   // a-pair (k2a, k2a+1); b-pair (k2a+1, k2a+2)
            c2 z0, z1, z2, m0, m1, m2;
            int i0 = NSK(k2a), i1 = NSK(k2a + 1), i2 = NSK(k2a + 2);
            int j0 = NSK((512 - k2a) & 511), j1 = NSK(511 - k2a), j2 = NSK(510 - k2a);
            z0.x = natR[i0]; z0.y = natI[i0];
            z1.x = natR[i1]; z1.y = natI[i1];
            z2.x = natR[i2]; z2.y = natI[i2];
            m0.x = natR[j0]; m0.y = natI[j0];
            m1.x = natR[j1]; m1.y = natI[j1];
            m2.x = natR[j2]; m2.y = natI[j2];

            float2 aRe = make_float2(0.5f * (z0.x + m0.x), 0.5f * (z1.x + m1.x));
            float2 aIm = make_float2(0.5f * (z0.y - m0.y), 0.5f * (z1.y - m1.y));
            float2 bRe = make_float2(0.5f * (z1.y + m1.y), 0.5f * (z2.y + m2.y));
            float2 bIm = make_float2(0.5f * (m1.x - z1.x), 0.5f * (m2.x - z2.x));
            *reinterpret_cast<float2*>(aBase + k2a)          = aRe;
            *reinterpret_cast<float2*>(aBase + CF + k2a)     = aIm;
            *reinterpret_cast<float2*>(bBase + k2a + 1)      = bRe;
            *reinterpret_cast<float2*>(bBase + CF + k2a + 1) = bIm;

            c2 saHi = cmul(sa, stepA);     // sv(ca, k2a+1)
            c2 sbHi = cmul(sb, stepB);     // sv(cb, k2a+2)
            *reinterpret_cast<float2*>(aBase + 2 * CF + k2a)     = make_float2(sa.x, saHi.x);
            *reinterpret_cast<float2*>(aBase + 3 * CF + k2a)     = make_float2(sa.y, saHi.y);
            *reinterpret_cast<float2*>(bBase + 2 * CF + k2a + 1) = make_float2(sb.x, sbHi.x);
            *reinterpret_cast<float2*>(bBase + 3 * CF + k2a + 1) = make_float2(sb.y, sbHi.y);
            sa = cmul(sa, rotA);
            sb = cmul(sb, rotB);
        }

        if (tau == 0) {   // edges: a @ k=256 (Nyquist), b @ k=0 (DC)
            int i256 = NSK(256);
            float zx = natR[i256], zy = natI[i256];
            aBase[256]          = zx;     // 0.5*(zx+zx)
            aBase[CF + 256]     = 0.f;    // Nyquist imag of real signal
            float s256, c256;
            __sincosf(SVCOEF * 256.f * dta, &s256, &c256);
            aBase[2 * CF + 256] = 0.5f * c256;
            aBase[3 * CF + 256] = 0.5f * s256;
            bBase[0]            = natI[NSK(0)];   // 0.5*(z0.y+z0.y)
            bBase[CF]           = 0.f;
            bBase[2 * CF]       = 0.5f;           // sv(k=0) = 1/2
            bBase[3 * CF]       = 0.f;
            (void)zy;
        }
    }
}

// ---------------------------------------------------------------------------
extern "C" void kernel_launch(void* const* d_in, const int* in_sizes, int n_in,
                              void* d_out, int out_size) {
    const float* x     = (const float*)d_in[0];
    const float* angle = (const float*)d_in[1];
    const float* mic   = (const float*)d_in[2];
    float* out = (float*)d_out;

    dim3 grid((TT + 3) / 4, BB * 2);
    stft_kernel<<<grid, 256>>>(x, angle, mic, out);
}

// round 17
// speedup vs baseline: 1.0781x; 1.0781x over previous
#include <cuda_runtime.h>
#include <math.h>

#define NFFT 512
#define HOP  128
#define LSIG 160000
#define BB   16
#define CC   4
#define TT   1251
#define FDIM 257
#define KFEAT (4 * CC * FDIM)   // 4112
#define CF   (CC * FDIM)        // 1028

#define PI_D 3.14159265358979323846
#define SVCOEF ((float)(-2.0 * PI_D * 16000.0 / (512.0 * 340.4)))

// pass1->pass2 skew stride (c2 units): 72 = 8 (mod 16) -> conflict-free
#define SDS 72
// pass2->pass3 exchange (c2 units): injective, conflict-free both phases
#define EX2(k0, kk, nn) (72 * (k0) + 8 * (kk) + ((nn) ^ (kk)))
// natural-order skew (c2 units): injective (monotone), conflict-free
#define NSK2(a) ((a) + 2 * ((a) >> 4))

struct c2 { float x, y; };

__device__ __forceinline__ c2 cmul(c2 a, c2 b){ c2 r; r.x = a.x*b.x - a.y*b.y; r.y = a.x*b.y + a.y*b.x; return r; }
__device__ __forceinline__ c2 cadd(c2 a, c2 b){ c2 r; r.x = a.x+b.x; r.y = a.y+b.y; return r; }
__device__ __forceinline__ c2 csub(c2 a, c2 b){ c2 r; r.x = a.x-b.x; r.y = a.y-b.y; return r; }
__device__ __forceinline__ c2 mulnegi(c2 a){ c2 r; r.x = a.y; r.y = -a.x; return r; }

// radix-8 DFT: o[k] = sum_j v[j] * w8^{j*k}, w8 = exp(-2*pi*i/8)
__device__ __forceinline__ void radix8(const c2* v, c2* o) {
    const float S = 0.70710678118654752f;
    c2 a0=cadd(v[0],v[4]), a1=csub(v[0],v[4]);
    c2 a2=cadd(v[2],v[6]), a3=csub(v[2],v[6]);
    c2 b0=cadd(v[1],v[5]), b1=csub(v[1],v[5]);
    c2 b2=cadd(v[3],v[7]), b3=csub(v[3],v[7]);
    c2 ia3 = mulnegi(a3), ib3 = mulnegi(b3);
    c2 c0=cadd(a0,a2), c1=csub(a0,a2);
    c2 e2=cadd(a1,ia3), e3=csub(a1,ia3);
    c2 d0=cadd(b0,b2), d1=csub(b0,b2);
    c2 d2=cadd(b1,ib3), d3=csub(b1,ib3);
    c2 w1d2; w1d2.x = S*(d2.x + d2.y); w1d2.y = S*(d2.y - d2.x);
    c2 w3d3; w3d3.x = S*(d3.y - d3.x); w3d3.y = -S*(d3.x + d3.y);
    c2 id1 = mulnegi(d1);
    o[0]=cadd(c0,d0);    o[4]=csub(c0,d0);
    o[2]=cadd(c1,id1);   o[6]=csub(c1,id1);
    o[1]=cadd(e2,w1d2);  o[5]=csub(e2,w1d2);
    o[3]=cadd(e3,w3d3);  o[7]=csub(e3,w3d3);
}

// ---------------------------------------------------------------------------
// Single fused kernel: TDOA (threads 0-63, rides existing barriers) + STFT
// (4 FFT units of 64 thr; 3 radix-8 register passes, conflict-free c2
// exchanges) + scalar coalesced epilogue with sv rotation chains.
// ---------------------------------------------------------------------------
__global__ void __launch_bounds__(256) stft_kernel(const float* __restrict__ x,
                                                   const float* __restrict__ angle,
                                                   const float* __restrict__ mic_pos,
                                                   float* __restrict__ out) {
    __shared__ c2 sd[4][576];        // p1->p2 skew 72; reused as nat (NSK2)
    __shared__ c2 ex[4][576];        // p2->p3 exchange (EX2)
    __shared__ float d2s[BB * CC];   // TDOA partials
    __shared__ float dts[CC];        // tdoa[c]

    const int tid = threadIdx.x;
    const int u   = tid >> 6;        // FFT unit 0..3
    const int tau = tid & 63;
    const int t   = blockIdx.x * 4 + u;
    const int by  = blockIdx.y;
    const int b   = by >> 1;
    const int pr  = by & 1;          // channel pair (2pr, 2pr+1)
    const bool active = (t < TT);

    c2* nat = sd[u];                 // aliased after pass-2 reads complete

    c2 v[8], o8[8];

    // ---- TDOA partials (threads 0-63) ----
    if (tid < BB * CC) {
        const int bb = tid >> 2;
        // exact fp32 values of sinf/cosf(float(pi/2)) — reference quirk
        const float sin90 = 1.0f;
        const float cos90 = -4.37113883e-08f;
        float rad = -angle[bb] * (float)(PI_D / 180.0);
        float sr_, cr_;
        sincosf(rad, &sr_, &cr_);
        float lx = cr_ * sin90;
        float ly = sr_ * sin90;
        float lz = cos90;              // DIST = 1.0
        const float* mp = mic_pos + tid * 3;
        float dx = mp[0] - lx, dy = mp[1] - ly, dz = mp[2] - lz;
        d2s[tid] = dx * dx + dy * dy + dz * dz;
    }

    // ---- pass 1: windowed load, radix-8 over n2, twiddle W64^{n1*k0} ----
    if (active) {
        const float S = 0.70710678118654752f;
        const float c8[8] = {1.f,  S, 0.f, -S, -1.f, -S,  0.f,  S};
        const float s8[8] = {0.f,  S, 1.f,  S,  0.f, -S, -1.f, -S};
        float sth, cth;
        __sincosf((float)(2.0 * PI_D / 512.0) * (float)tau, &sth, &cth);

        const float* xa = x + (size_t)(b * CC + 2 * pr) * LSIG;
        const float* xb = xa + LSIG;
        const int p0 = t * HOP - 256;
        if (t >= 2 && t <= 1248) {           // interior: no reflection possible
#pragma unroll
            for (int n2 = 0; n2 < 8; n2++) {
                int si = p0 + n2 * 64 + tau;
                float cosn = c8[n2] * cth - s8[n2] * sth;    // cos(2*pi*n/512)
                float w = 0.5f - 0.5f * cosn;                // Hann
                v[n2].x = xa[si] * w;
                v[n2].y = xb[si] * w;
            }
        } else {
#pragma unroll
            for (int n2 = 0; n2 < 8; n2++) {
                int p = p0 + n2 * 64 + tau;
                int si = (p < 0) ? -p : ((p >= LSIG) ? 2 * LSIG - 2 - p : p);
                float cosn = c8[n2] * cth - s8[n2] * sth;
                float w = 0.5f - 0.5f * cosn;
                v[n2].x = xa[si] * w;
                v[n2].y = xb[si] * w;
            }
        }
        radix8(v, o8);
        int n1 = tau >> 3;
        float ss, cs;
        __sincosf((float)(-2.0 * PI_D / 64.0) * (float)n1, &ss, &cs);
        c2 step; step.x = cs; step.y = ss;                   // W64^{n1}
        c2 w; w.x = 1.f; w.y = 0.f;
#pragma unroll
        for (int k0 = 0; k0 < 8; k0++) {
            sd[u][k0 * SDS + tau] = cmul(o8[k0], w);         // * W64^{n1*k0}
            w = cmul(w, step);
        }
    }
    __syncthreads();

    // ---- TDOA reduce (rides the pass-1 barrier; read after barrier 3) ----
    if (tid < CC) {
        float ssum = 0.f;
        for (int bb = 0; bb < BB; bb++) ssum += d2s[bb * CC + tid];
        dts[tid] = sqrtf(ssum);
    }

    // ---- pass 2: radix-8 over n1, twiddle, write c2 exchange ----
    if (active) {
        const int k0 = tau >> 3;
        const int n0 = tau & 7;
#pragma unroll
        for (int n1 = 0; n1 < 8; n1++) v[n1] = sd[u][k0 * SDS + n1 * 8 + n0];
        radix8(v, o8);
        float s0, c0, ss, cs;
        __sincosf((float)(-2.0 * PI_D / 512.0) * (float)(n0 * k0), &s0, &c0);
        __sincosf((float)(-2.0 * PI_D / 64.0) * (float)n0, &ss, &cs);
        c2 w;    w.x = c0;   w.y = s0;                       // W512^{n0*k0}
        c2 step; step.x = cs; step.y = ss;                   // W64^{n0}
#pragma unroll
        for (int k1 = 0; k1 < 8; k1++) {
            ex[u][EX2(k0, k1, n0)] = cmul(o8[k1], w);
            w = cmul(w, step);
        }
    }
    __syncthreads();   // pass-2 reads of sd complete -> sd reusable as nat

    // ---- pass 3: read exchange, radix-8 over n0, NSK2 store into nat ----
    if (active) {
        const int k0 = tau >> 3;
        const int l  = tau & 7;      // = k1
#pragma unroll
        for (int n0 = 0; n0 < 8; n0++) v[n0] = ex[u][EX2(k0, l, n0)];
        radix8(v, o8);               // o8[k2] = X[64*k2 + 8*l + k0]
#pragma unroll
        for (int k2 = 0; k2 < 8; k2++) {
            int a = k2 * 64 + l * 8 + k0;
            nat[NSK2(a)] = o8[k2];
        }
    }
    __syncthreads();

    // ---- unpack 2 real spectra + write X groups + computed SV groups ----
    if (active) {
        float* row = out + ((size_t)b * TT + t) * KFEAT;
        const int ca = 2 * pr, cb = 2 * pr + 1;
        const float dta = dts[ca] - dts[0];
        const float dtb = dts[cb] - dts[0];
        float* aBase = row + ca * FDIM;
        float* bBase = row + cb * FDIM;
        // incremental steering-vector rotation: sv(k+64) = sv(k) * rot
        c2 sva, svb, rota, rotb;
        __sincosf(SVCOEF * (float)tau * dta, &sva.y, &sva.x);
        __sincosf(SVCOEF * (float)tau * dtb, &svb.y, &svb.x);
        __sincosf(SVCOEF * 64.f * dta, &rota.y, &rota.x);
        __sincosf(SVCOEF * 64.f * dtb, &rotb.y, &rotb.x);
        for (int k = tau; k <= 256; k += 64) {
            int mk = (512 - k) & 511;
            c2 zk = nat[NSK2(k)];
            c2 zm = nat[NSK2(mk)];
            aBase[k]          = 0.5f * (zk.x + zm.x);   // A.re
            aBase[CF + k]     = 0.5f * (zk.y - zm.y);   // A.im
            bBase[k]          = 0.5f * (zk.y + zm.y);   // B.re
            bBase[CF + k]     = 0.5f * (zm.x - zk.x);   // B.im
            aBase[2 * CF + k] = 0.5f * sva.x;           // sv.re / ||sv||
            aBase[3 * CF + k] = 0.5f * sva.y;           // sv.im
            bBase[2 * CF + k] = 0.5f * svb.x;
            bBase[3 * CF + k] = 0.5f * svb.y;
            sva = cmul(sva, rota);
            svb = cmul(svb, rotb);
        }
    }
}

// ---------------------------------------------------------------------------
extern "C" void kernel_launch(void* const* d_in, const int* in_sizes, int n_in,
                              void* d_out, int out_size) {
    const float* x     = (const float*)d_in[0];
    const float* angle = (const float*)d_in[1];
    const float* mic   = (const float*)d_in[2];
    float* out = (float*)d_out;

    dim3 grid((TT + 3) / 4, BB * 2);
    stft_kernel<<<grid, 256>>>(x, angle, mic, out);
}